// round 2
// baseline (speedup 1.0000x reference)
#include <cuda_runtime.h>
#include <math.h>

// Problem constants
#define T_TOK 2048      // B*S tokens
#define D_IN  1024      // model dim
#define E_NUM 16        // routed experts
#define TOPK  2
#define H_DIM 512       // expert intermediate
#define HS_DIM 1024     // shared expert intermediate (2*H)
#define NA    (T_TOK * TOPK)   // 4096 assignments

// ---------------- scratch (device globals, allocation-free) ----------------
__device__ float g_w[NA];            // routing weight per assignment
__device__ int   g_eidx[NA];         // expert per assignment
__device__ int   g_counts[E_NUM];
__device__ int   g_offsets[E_NUM + 1];
__device__ int   g_perm[NA];         // sorted-by-expert assignment ids
__device__ int   g_pos[NA];          // assignment id -> sorted position
__device__ float g_h1raw[(size_t)NA * 1024];     // routed fc1 raw (u|g)
__device__ float g_h1act[(size_t)NA * 512];      // routed fc1 activated
__device__ float g_h2buf[(size_t)NA * 1024];     // routed fc2 per-assignment (weighted)
__device__ float g_hsraw[(size_t)T_TOK * 2048];  // shared fc1 raw
__device__ float g_hsact[(size_t)T_TOK * 1024];  // shared fc1 activated

// ---------------- gate: scores=softmax(x@Wg^T), top-2 ----------------
__global__ void zero_kernel() {
    if (threadIdx.x < E_NUM) g_counts[threadIdx.x] = 0;
}

__global__ void gate_kernel(const float* __restrict__ x,
                            const float* __restrict__ Wg) {
    int t = blockIdx.x;
    const float* xr = x + (size_t)t * D_IN;
    __shared__ float sx[D_IN];
    for (int i = threadIdx.x; i < D_IN; i += 128) sx[i] = xr[i];
    __syncthreads();

    int e = threadIdx.x >> 3;      // 16 experts
    int sub = threadIdx.x & 7;     // 8 threads each
    const float* wr = Wg + (size_t)e * D_IN;
    float s = 0.f;
    for (int i = sub; i < D_IN; i += 8) s = fmaf(sx[i], wr[i], s);
    // reduce within group of 8
    for (int o = 4; o; o >>= 1) s += __shfl_down_sync(0xffffffffu, s, o, 8);

    __shared__ float sc[E_NUM];
    if (sub == 0) sc[e] = s;
    __syncthreads();

    if (threadIdx.x == 0) {
        float mx = sc[0];
        #pragma unroll
        for (int i = 1; i < E_NUM; i++) mx = fmaxf(mx, sc[i]);
        float p[E_NUM];
        float den = 0.f;
        #pragma unroll
        for (int i = 0; i < E_NUM; i++) { p[i] = expf(sc[i] - mx); den += p[i]; }
        int i1 = 0; float v1 = p[0];
        #pragma unroll
        for (int i = 1; i < E_NUM; i++) if (p[i] > v1) { v1 = p[i]; i1 = i; }
        int i2 = -1; float v2 = -1.f;
        #pragma unroll
        for (int i = 0; i < E_NUM; i++)
            if (i != i1 && p[i] > v2) { v2 = p[i]; i2 = i; }
        float inv = 1.f / den;
        g_eidx[t * 2 + 0] = i1; g_w[t * 2 + 0] = v1 * inv;
        g_eidx[t * 2 + 1] = i2; g_w[t * 2 + 1] = v2 * inv;
        atomicAdd(&g_counts[i1], 1);
        atomicAdd(&g_counts[i2], 1);
    }
}

__global__ void scan_kernel() {
    if (threadIdx.x == 0) {
        int a = 0;
        for (int e = 0; e < E_NUM; e++) { g_offsets[e] = a; a += g_counts[e]; }
        g_offsets[E_NUM] = a;
    }
}

// stable per-expert compaction (deterministic ordering)
__global__ void compact_kernel() {
    int e = blockIdx.x;
    int base = g_offsets[e];
    __shared__ int warp_tot[8];
    __shared__ int running;
    if (threadIdx.x == 0) running = 0;
    __syncthreads();
    int lane = threadIdx.x & 31, wid = threadIdx.x >> 5;
    for (int c = 0; c < NA; c += 256) {
        int i = c + threadIdx.x;
        bool f = (g_eidx[i] == e);
        unsigned bal = __ballot_sync(0xffffffffu, f);
        int pre = __popc(bal & ((1u << lane) - 1u));
        if (lane == 0) warp_tot[wid] = __popc(bal);
        __syncthreads();
        int woff = 0, ctot = 0;
        #pragma unroll
        for (int w = 0; w < 8; w++) {
            int v = warp_tot[w];
            if (w < wid) woff += v;
            ctot += v;
        }
        if (f) {
            int pos = base + running + woff + pre;
            g_perm[pos] = i;
            g_pos[i] = pos;
        }
        __syncthreads();
        if (threadIdx.x == 0) running += ctot;
        __syncthreads();
    }
}

// ---------------- 128x128x8 fp32 SGEMM, 8x8 per thread ----------------
// MODE 0: routed fc1  : A = x gathered by perm,   B = W1[e],  C = g_h1raw
// MODE 1: routed fc2  : A = g_h1act (sorted),     B = W2[e],  C = g_h2buf (w-scaled)
// MODE 2: shared fc1  : A = x,                    B = Ws1,    C = g_hsraw
// MODE 3: shared fc2  : A = g_hsact,              B = Ws2,    C = out
#define BM 128
#define BN 128
#define BK 8

template <int MODE>
__global__ __launch_bounds__(256)
void gemm_kernel(const float* __restrict__ A,
                 const float* __restrict__ Bmat,
                 float* __restrict__ Cout) {
    int e = 0, cnt, base = 0, Kdim, ldb;
    const float* Bp;
    if constexpr (MODE == 0) {
        e = blockIdx.z; cnt = g_counts[e]; base = g_offsets[e];
        Kdim = 1024; ldb = 1024; Bp = Bmat + (size_t)e * 1024 * 1024;
    } else if constexpr (MODE == 1) {
        e = blockIdx.z; cnt = g_counts[e]; base = g_offsets[e];
        Kdim = 512; ldb = 1024; Bp = Bmat + (size_t)e * 512 * 1024;
    } else if constexpr (MODE == 2) {
        cnt = T_TOK; Kdim = 1024; ldb = 2048; Bp = Bmat;
    } else {
        cnt = T_TOK; Kdim = 1024; ldb = 1024; Bp = Bmat;
    }
    int m0 = blockIdx.y * BM;
    if (m0 >= cnt) return;
    int n0 = blockIdx.x * BN;

    __shared__ float As[BK][BM + 4];   // +4 pad: conflict-free transposed stores
    __shared__ float Bs[BK][BN];

    int tid = threadIdx.x;
    int arow = tid >> 1;
    int acol = (tid & 1) << 2;
    int brow = tid >> 5;
    int bcol = (tid & 31) << 2;

    const float* aptr = nullptr;
    int grow = m0 + arow;
    bool avalid = grow < cnt;
    if (avalid) {
        if constexpr (MODE == 0) {
            int tok = g_perm[base + grow] >> 1;
            aptr = A + (size_t)tok * 1024;
        } else if constexpr (MODE == 1) {
            aptr = g_h1act + (size_t)(base + grow) * 512;
        } else if constexpr (MODE == 2) {
            aptr = A + (size_t)grow * 1024;
        } else {
            aptr = g_hsact + (size_t)grow * 1024;
        }
    }

    float acc[8][8];
    #pragma unroll
    for (int i = 0; i < 8; i++)
        #pragma unroll
        for (int j = 0; j < 8; j++) acc[i][j] = 0.f;

    int ty = tid >> 4, tx = tid & 15;

    for (int k0 = 0; k0 < Kdim; k0 += BK) {
        float4 av = make_float4(0.f, 0.f, 0.f, 0.f);
        if (avalid) av = *reinterpret_cast<const float4*>(aptr + k0 + acol);
        As[acol + 0][arow] = av.x;
        As[acol + 1][arow] = av.y;
        As[acol + 2][arow] = av.z;
        As[acol + 3][arow] = av.w;
        *reinterpret_cast<float4*>(&Bs[brow][bcol]) =
            *reinterpret_cast<const float4*>(Bp + (size_t)(k0 + brow) * ldb + n0 + bcol);
        __syncthreads();
        #pragma unroll
        for (int k = 0; k < BK; k++) {
            float a[8], b[8];
            *reinterpret_cast<float4*>(a)     = *reinterpret_cast<const float4*>(&As[k][ty * 8]);
            *reinterpret_cast<float4*>(a + 4) = *reinterpret_cast<const float4*>(&As[k][ty * 8 + 4]);
            *reinterpret_cast<float4*>(b)     = *reinterpret_cast<const float4*>(&Bs[k][tx * 8]);
            *reinterpret_cast<float4*>(b + 4) = *reinterpret_cast<const float4*>(&Bs[k][tx * 8 + 4]);
            #pragma unroll
            for (int i = 0; i < 8; i++)
                #pragma unroll
                for (int j = 0; j < 8; j++)
                    acc[i][j] = fmaf(a[i], b[j], acc[i][j]);
        }
        __syncthreads();
    }

    #pragma unroll
    for (int i = 0; i < 8; i++) {
        int row = m0 + ty * 8 + i;
        if (row >= cnt) break;
        int col = n0 + tx * 8;
        if constexpr (MODE == 0) {
            float* dst = g_h1raw + (size_t)(base + row) * 1024 + col;
            *reinterpret_cast<float4*>(dst)     = make_float4(acc[i][0], acc[i][1], acc[i][2], acc[i][3]);
            *reinterpret_cast<float4*>(dst + 4) = make_float4(acc[i][4], acc[i][5], acc[i][6], acc[i][7]);
        } else if constexpr (MODE == 1) {
            float w = g_w[g_perm[base + row]];
            float* dst = g_h2buf + (size_t)(base + row) * 1024 + col;
            *reinterpret_cast<float4*>(dst)     = make_float4(w * acc[i][0], w * acc[i][1], w * acc[i][2], w * acc[i][3]);
            *reinterpret_cast<float4*>(dst + 4) = make_float4(w * acc[i][4], w * acc[i][5], w * acc[i][6], w * acc[i][7]);
        } else if constexpr (MODE == 2) {
            float* dst = g_hsraw + (size_t)row * 2048 + col;
            *reinterpret_cast<float4*>(dst)     = make_float4(acc[i][0], acc[i][1], acc[i][2], acc[i][3]);
            *reinterpret_cast<float4*>(dst + 4) = make_float4(acc[i][4], acc[i][5], acc[i][6], acc[i][7]);
        } else {
            float* dst = Cout + (size_t)row * 1024 + col;
            *reinterpret_cast<float4*>(dst)     = make_float4(acc[i][0], acc[i][1], acc[i][2], acc[i][3]);
            *reinterpret_cast<float4*>(dst + 4) = make_float4(acc[i][4], acc[i][5], acc[i][6], acc[i][7]);
        }
    }
}

// ---------------- activations: u * silu(g) ----------------
__device__ __forceinline__ float silu_mul(float u, float g) {
    return u * (g / (1.f + expf(-g)));
}

__global__ void act_routed_kernel() {
    int i = blockIdx.x * blockDim.x + threadIdx.x;   // over NA*512/4
    if (i >= NA * 128) return;
    int p = i >> 7, h4 = i & 127;
    const float* rowp = g_h1raw + (size_t)p * 1024;
    float4 u = reinterpret_cast<const float4*>(rowp)[h4];
    float4 g = reinterpret_cast<const float4*>(rowp + 512)[h4];
    float4 r;
    r.x = silu_mul(u.x, g.x); r.y = silu_mul(u.y, g.y);
    r.z = silu_mul(u.z, g.z); r.w = silu_mul(u.w, g.w);
    reinterpret_cast<float4*>(g_h1act + (size_t)p * 512)[h4] = r;
}

__global__ void act_shared_kernel() {
    int i = blockIdx.x * blockDim.x + threadIdx.x;   // over T*1024/4
    if (i >= T_TOK * 256) return;
    int t = i >> 8, h4 = i & 255;
    const float* rowp = g_hsraw + (size_t)t * 2048;
    float4 u = reinterpret_cast<const float4*>(rowp)[h4];
    float4 g = reinterpret_cast<const float4*>(rowp + 1024)[h4];
    float4 r;
    r.x = silu_mul(u.x, g.x); r.y = silu_mul(u.y, g.y);
    r.z = silu_mul(u.z, g.z); r.w = silu_mul(u.w, g.w);
    reinterpret_cast<float4*>(g_hsact + (size_t)t * 1024)[h4] = r;
}

// ---------------- deterministic combine: out += routed(k0) + routed(k1) ----
__global__ void combine_kernel(float* __restrict__ out) {
    int i = blockIdx.x * blockDim.x + threadIdx.x;   // over T*1024/4
    if (i >= T_TOK * 256) return;
    int t = i >> 8, c4 = i & 255;
    int p0 = g_pos[2 * t + 0];
    int p1 = g_pos[2 * t + 1];
    float4 a = reinterpret_cast<const float4*>(g_h2buf + (size_t)p0 * 1024)[c4];
    float4 b = reinterpret_cast<const float4*>(g_h2buf + (size_t)p1 * 1024)[c4];
    float4* o = reinterpret_cast<float4*>(out + (size_t)t * 1024) + c4;
    float4 v = *o;
    v.x += a.x + b.x; v.y += a.y + b.y; v.z += a.z + b.z; v.w += a.w + b.w;
    *o = v;
}

// ---------------- launch ----------------
extern "C" void kernel_launch(void* const* d_in, const int* in_sizes, int n_in,
                              void* d_out, int out_size) {
    (void)in_sizes; (void)n_in; (void)out_size;
    const float* x   = (const float*)d_in[0];
    const float* Wg  = (const float*)d_in[1];
    const float* W1  = (const float*)d_in[2];
    const float* W2  = (const float*)d_in[3];
    const float* Ws1 = (const float*)d_in[4];
    const float* Ws2 = (const float*)d_in[5];
    float* out = (float*)d_out;

    zero_kernel<<<1, 32>>>();
    gate_kernel<<<T_TOK, 128>>>(x, Wg);
    scan_kernel<<<1, 32>>>();
    compact_kernel<<<E_NUM, 256>>>();

    // routed fc1: per-expert [cnt,1024] x [1024,1024]
    gemm_kernel<0><<<dim3(1024 / BN, T_TOK / BM, E_NUM), 256>>>(x, W1, nullptr);
    act_routed_kernel<<<(NA * 128 + 255) / 256, 256>>>();
    // routed fc2: per-expert [cnt,512] x [512,1024] -> weighted per-assignment
    gemm_kernel<1><<<dim3(1024 / BN, T_TOK / BM, E_NUM), 256>>>(nullptr, W2, nullptr);

    // shared fc1: [2048,1024] x [1024,2048]
    gemm_kernel<2><<<dim3(2048 / BN, T_TOK / BM, 1), 256>>>(x, Ws1, nullptr);
    act_shared_kernel<<<(T_TOK * 256 + 255) / 256, 256>>>();
    // shared fc2: [2048,1024] x [1024,1024] -> out (plain store, defines out)
    gemm_kernel<3><<<dim3(1024 / BN, T_TOK / BM, 1), 256>>>(nullptr, Ws2, out);

    // deterministic final combine
    combine_kernel<<<(T_TOK * 256 + 255) / 256, 256>>>(out);
}

// round 3
// speedup vs baseline: 1.0006x; 1.0006x over previous
#include <cuda_runtime.h>
#include <math.h>

// Problem constants
#define T_TOK 2048      // B*S tokens
#define D_IN  1024      // model dim
#define E_NUM 16        // routed experts
#define TOPK  2
#define H_DIM 512       // expert intermediate
#define HS_DIM 1024     // shared expert intermediate (2*H)
#define NA    (T_TOK * TOPK)   // 4096 assignments

// ---------------- scratch (device globals, allocation-free) ----------------
__device__ float g_w[NA];            // routing weight per assignment
__device__ int   g_eidx[NA];         // expert per assignment
__device__ int   g_counts[E_NUM];
__device__ int   g_offsets[E_NUM + 1];
__device__ int   g_perm[NA];         // sorted-by-expert assignment ids
__device__ int   g_pos[NA];          // assignment id -> sorted position
__device__ float g_h1raw[(size_t)NA * 1024];     // routed fc1 raw (u|g)
__device__ float g_h1act[(size_t)NA * 512];      // routed fc1 activated
__device__ float g_h2buf[(size_t)NA * 1024];     // routed fc2 per-assignment (weighted)
__device__ float g_hsraw[(size_t)T_TOK * 2048];  // shared fc1 raw
__device__ float g_hsact[(size_t)T_TOK * 1024];  // shared fc1 activated

// ---------------- gate: scores=softmax(x@Wg^T), top-2 ----------------
__global__ void zero_kernel() {
    if (threadIdx.x < E_NUM) g_counts[threadIdx.x] = 0;
}

__global__ void gate_kernel(const float* __restrict__ x,
                            const float* __restrict__ Wg) {
    int t = blockIdx.x;
    const float* xr = x + (size_t)t * D_IN;
    __shared__ float sx[D_IN];
    for (int i = threadIdx.x; i < D_IN; i += 128) sx[i] = xr[i];
    __syncthreads();

    int e = threadIdx.x >> 3;      // 16 experts
    int sub = threadIdx.x & 7;     // 8 threads each
    const float* wr = Wg + (size_t)e * D_IN;
    float s = 0.f;
    for (int i = sub; i < D_IN; i += 8) s = fmaf(sx[i], wr[i], s);
    // reduce within group of 8
    for (int o = 4; o; o >>= 1) s += __shfl_down_sync(0xffffffffu, s, o, 8);

    __shared__ float sc[E_NUM];
    if (sub == 0) sc[e] = s;
    __syncthreads();

    if (threadIdx.x == 0) {
        float mx = sc[0];
        #pragma unroll
        for (int i = 1; i < E_NUM; i++) mx = fmaxf(mx, sc[i]);
        float p[E_NUM];
        float den = 0.f;
        #pragma unroll
        for (int i = 0; i < E_NUM; i++) { p[i] = expf(sc[i] - mx); den += p[i]; }
        int i1 = 0; float v1 = p[0];
        #pragma unroll
        for (int i = 1; i < E_NUM; i++) if (p[i] > v1) { v1 = p[i]; i1 = i; }
        int i2 = -1; float v2 = -1.f;
        #pragma unroll
        for (int i = 0; i < E_NUM; i++)
            if (i != i1 && p[i] > v2) { v2 = p[i]; i2 = i; }
        float inv = 1.f / den;
        g_eidx[t * 2 + 0] = i1; g_w[t * 2 + 0] = v1 * inv;
        g_eidx[t * 2 + 1] = i2; g_w[t * 2 + 1] = v2 * inv;
        atomicAdd(&g_counts[i1], 1);
        atomicAdd(&g_counts[i2], 1);
    }
}

__global__ void scan_kernel() {
    if (threadIdx.x == 0) {
        int a = 0;
        for (int e = 0; e < E_NUM; e++) { g_offsets[e] = a; a += g_counts[e]; }
        g_offsets[E_NUM] = a;
    }
}

// stable per-expert compaction (deterministic ordering)
__global__ void compact_kernel() {
    int e = blockIdx.x;
    int base = g_offsets[e];
    __shared__ int warp_tot[8];
    __shared__ int running;
    if (threadIdx.x == 0) running = 0;
    __syncthreads();
    int lane = threadIdx.x & 31, wid = threadIdx.x >> 5;
    for (int c = 0; c < NA; c += 256) {
        int i = c + threadIdx.x;
        bool f = (g_eidx[i] == e);
        unsigned bal = __ballot_sync(0xffffffffu, f);
        int pre = __popc(bal & ((1u << lane) - 1u));
        if (lane == 0) warp_tot[wid] = __popc(bal);
        __syncthreads();
        int woff = 0, ctot = 0;
        #pragma unroll
        for (int w = 0; w < 8; w++) {
            int v = warp_tot[w];
            if (w < wid) woff += v;
            ctot += v;
        }
        if (f) {
            int pos = base + running + woff + pre;
            g_perm[pos] = i;
            g_pos[i] = pos;
        }
        __syncthreads();
        if (threadIdx.x == 0) running += ctot;
        __syncthreads();
    }
}

// ---------------- 128x128x8 fp32 SGEMM, 8x8 per thread ----------------
// MODE 0: routed fc1  : A = x gathered by perm,   B = W1[e],  C = g_h1raw
// MODE 1: routed fc2  : A = g_h1act (sorted),     B = W2[e],  C = g_h2buf (w-scaled)
// MODE 2: shared fc1  : A = x,                    B = Ws1,    C = g_hsraw
// MODE 3: shared fc2  : A = g_hsact,              B = Ws2,    C = out
#define BM 128
#define BN 128
#define BK 8

template <int MODE>
__global__ __launch_bounds__(256)
void gemm_kernel(const float* __restrict__ A,
                 const float* __restrict__ Bmat,
                 float* __restrict__ Cout) {
    int e = 0, cnt, base = 0, Kdim, ldb;
    const float* Bp;
    if constexpr (MODE == 0) {
        e = blockIdx.z; cnt = g_counts[e]; base = g_offsets[e];
        Kdim = 1024; ldb = 1024; Bp = Bmat + (size_t)e * 1024 * 1024;
    } else if constexpr (MODE == 1) {
        e = blockIdx.z; cnt = g_counts[e]; base = g_offsets[e];
        Kdim = 512; ldb = 1024; Bp = Bmat + (size_t)e * 512 * 1024;
    } else if constexpr (MODE == 2) {
        cnt = T_TOK; Kdim = 1024; ldb = 2048; Bp = Bmat;
    } else {
        cnt = T_TOK; Kdim = 1024; ldb = 1024; Bp = Bmat;
    }
    int m0 = blockIdx.y * BM;
    if (m0 >= cnt) return;
    int n0 = blockIdx.x * BN;

    __shared__ float As[BK][BM + 4];   // +4 pad: conflict-free transposed stores
    __shared__ float Bs[BK][BN];

    int tid = threadIdx.x;
    int arow = tid >> 1;
    int acol = (tid & 1) << 2;
    int brow = tid >> 5;
    int bcol = (tid & 31) << 2;

    const float* aptr = nullptr;
    int grow = m0 + arow;
    bool avalid = grow < cnt;
    if (avalid) {
        if constexpr (MODE == 0) {
            int tok = g_perm[base + grow] >> 1;
            aptr = A + (size_t)tok * 1024;
        } else if constexpr (MODE == 1) {
            aptr = g_h1act + (size_t)(base + grow) * 512;
        } else if constexpr (MODE == 2) {
            aptr = A + (size_t)grow * 1024;
        } else {
            aptr = g_hsact + (size_t)grow * 1024;
        }
    }

    float acc[8][8];
    #pragma unroll
    for (int i = 0; i < 8; i++)
        #pragma unroll
        for (int j = 0; j < 8; j++) acc[i][j] = 0.f;

    int ty = tid >> 4, tx = tid & 15;

    for (int k0 = 0; k0 < Kdim; k0 += BK) {
        float4 av = make_float4(0.f, 0.f, 0.f, 0.f);
        if (avalid) av = *reinterpret_cast<const float4*>(aptr + k0 + acol);
        As[acol + 0][arow] = av.x;
        As[acol + 1][arow] = av.y;
        As[acol + 2][arow] = av.z;
        As[acol + 3][arow] = av.w;
        *reinterpret_cast<float4*>(&Bs[brow][bcol]) =
            *reinterpret_cast<const float4*>(Bp + (size_t)(k0 + brow) * ldb + n0 + bcol);
        __syncthreads();
        #pragma unroll
        for (int k = 0; k < BK; k++) {
            float a[8], b[8];
            *reinterpret_cast<float4*>(a)     = *reinterpret_cast<const float4*>(&As[k][ty * 8]);
            *reinterpret_cast<float4*>(a + 4) = *reinterpret_cast<const float4*>(&As[k][ty * 8 + 4]);
            *reinterpret_cast<float4*>(b)     = *reinterpret_cast<const float4*>(&Bs[k][tx * 8]);
            *reinterpret_cast<float4*>(b + 4) = *reinterpret_cast<const float4*>(&Bs[k][tx * 8 + 4]);
            #pragma unroll
            for (int i = 0; i < 8; i++)
                #pragma unroll
                for (int j = 0; j < 8; j++)
                    acc[i][j] = fmaf(a[i], b[j], acc[i][j]);
        }
        __syncthreads();
    }

    #pragma unroll
    for (int i = 0; i < 8; i++) {
        int row = m0 + ty * 8 + i;
        if (row >= cnt) break;
        int col = n0 + tx * 8;
        if constexpr (MODE == 0) {
            float* dst = g_h1raw + (size_t)(base + row) * 1024 + col;
            *reinterpret_cast<float4*>(dst)     = make_float4(acc[i][0], acc[i][1], acc[i][2], acc[i][3]);
            *reinterpret_cast<float4*>(dst + 4) = make_float4(acc[i][4], acc[i][5], acc[i][6], acc[i][7]);
        } else if constexpr (MODE == 1) {
            float w = g_w[g_perm[base + row]];
            float* dst = g_h2buf + (size_t)(base + row) * 1024 + col;
            *reinterpret_cast<float4*>(dst)     = make_float4(w * acc[i][0], w * acc[i][1], w * acc[i][2], w * acc[i][3]);
            *reinterpret_cast<float4*>(dst + 4) = make_float4(w * acc[i][4], w * acc[i][5], w * acc[i][6], w * acc[i][7]);
        } else if constexpr (MODE == 2) {
            float* dst = g_hsraw + (size_t)row * 2048 + col;
            *reinterpret_cast<float4*>(dst)     = make_float4(acc[i][0], acc[i][1], acc[i][2], acc[i][3]);
            *reinterpret_cast<float4*>(dst + 4) = make_float4(acc[i][4], acc[i][5], acc[i][6], acc[i][7]);
        } else {
            float* dst = Cout + (size_t)row * 1024 + col;
            *reinterpret_cast<float4*>(dst)     = make_float4(acc[i][0], acc[i][1], acc[i][2], acc[i][3]);
            *reinterpret_cast<float4*>(dst + 4) = make_float4(acc[i][4], acc[i][5], acc[i][6], acc[i][7]);
        }
    }
}

// ---------------- activations: u * silu(g) ----------------
__device__ __forceinline__ float silu_mul(float u, float g) {
    return u * (g / (1.f + expf(-g)));
}

__global__ void act_routed_kernel() {
    int i = blockIdx.x * blockDim.x + threadIdx.x;   // over NA*512/4
    if (i >= NA * 128) return;
    int p = i >> 7, h4 = i & 127;
    const float* rowp = g_h1raw + (size_t)p * 1024;
    float4 u = reinterpret_cast<const float4*>(rowp)[h4];
    float4 g = reinterpret_cast<const float4*>(rowp + 512)[h4];
    float4 r;
    r.x = silu_mul(u.x, g.x); r.y = silu_mul(u.y, g.y);
    r.z = silu_mul(u.z, g.z); r.w = silu_mul(u.w, g.w);
    reinterpret_cast<float4*>(g_h1act + (size_t)p * 512)[h4] = r;
}

__global__ void act_shared_kernel() {
    int i = blockIdx.x * blockDim.x + threadIdx.x;   // over T*1024/4
    if (i >= T_TOK * 256) return;
    int t = i >> 8, h4 = i & 255;
    const float* rowp = g_hsraw + (size_t)t * 2048;
    float4 u = reinterpret_cast<const float4*>(rowp)[h4];
    float4 g = reinterpret_cast<const float4*>(rowp + 1024)[h4];
    float4 r;
    r.x = silu_mul(u.x, g.x); r.y = silu_mul(u.y, g.y);
    r.z = silu_mul(u.z, g.z); r.w = silu_mul(u.w, g.w);
    reinterpret_cast<float4*>(g_hsact + (size_t)t * 1024)[h4] = r;
}

// ---------------- deterministic combine: out += routed(k0) + routed(k1) ----
__global__ void combine_kernel(float* __restrict__ out) {
    int i = blockIdx.x * blockDim.x + threadIdx.x;   // over T*1024/4
    if (i >= T_TOK * 256) return;
    int t = i >> 8, c4 = i & 255;
    int p0 = g_pos[2 * t + 0];
    int p1 = g_pos[2 * t + 1];
    float4 a = reinterpret_cast<const float4*>(g_h2buf + (size_t)p0 * 1024)[c4];
    float4 b = reinterpret_cast<const float4*>(g_h2buf + (size_t)p1 * 1024)[c4];
    float4* o = reinterpret_cast<float4*>(out + (size_t)t * 1024) + c4;
    float4 v = *o;
    v.x += a.x + b.x; v.y += a.y + b.y; v.z += a.z + b.z; v.w += a.w + b.w;
    *o = v;
}

// ---------------- launch ----------------
extern "C" void kernel_launch(void* const* d_in, const int* in_sizes, int n_in,
                              void* d_out, int out_size) {
    (void)in_sizes; (void)n_in; (void)out_size;
    const float* x   = (const float*)d_in[0];
    const float* Wg  = (const float*)d_in[1];
    const float* W1  = (const float*)d_in[2];
    const float* W2  = (const float*)d_in[3];
    const float* Ws1 = (const float*)d_in[4];
    const float* Ws2 = (const float*)d_in[5];
    float* out = (float*)d_out;

    zero_kernel<<<1, 32>>>();
    gate_kernel<<<T_TOK, 128>>>(x, Wg);
    scan_kernel<<<1, 32>>>();
    compact_kernel<<<E_NUM, 256>>>();

    // routed fc1: per-expert [cnt,1024] x [1024,1024]
    gemm_kernel<0><<<dim3(1024 / BN, T_TOK / BM, E_NUM), 256>>>(x, W1, nullptr);
    act_routed_kernel<<<(NA * 128 + 255) / 256, 256>>>();
    // routed fc2: per-expert [cnt,512] x [512,1024] -> weighted per-assignment
    gemm_kernel<1><<<dim3(1024 / BN, T_TOK / BM, E_NUM), 256>>>(nullptr, W2, nullptr);

    // shared fc1: [2048,1024] x [1024,2048]
    gemm_kernel<2><<<dim3(2048 / BN, T_TOK / BM, 1), 256>>>(x, Ws1, nullptr);
    act_shared_kernel<<<(T_TOK * 256 + 255) / 256, 256>>>();
    // shared fc2: [2048,1024] x [1024,1024] -> out (plain store, defines out)
    gemm_kernel<3><<<dim3(1024 / BN, T_TOK / BM, 1), 256>>>(nullptr, Ws2, out);

    // deterministic final combine
    combine_kernel<<<(T_TOK * 256 + 255) / 256, 256>>>(out);
}

// round 4
// speedup vs baseline: 3.1807x; 3.1789x over previous
#include <cuda_runtime.h>
#include <math.h>
#include <stdint.h>

// Problem constants
#define T_TOK 2048      // B*S tokens
#define D_IN  1024      // model dim
#define E_NUM 16        // routed experts
#define TOPK  2
#define H_DIM 512       // expert intermediate
#define HS_DIM 1024     // shared expert hidden (2*H)
#define NA    (T_TOK * TOPK)   // 4096 assignments

// ---------------- scratch (device globals, allocation-free) ----------------
__device__ float g_w[NA];
__device__ int   g_eidx[NA];
__device__ int   g_counts[E_NUM];
__device__ int   g_offsets[E_NUM + 1];
__device__ int   g_perm[NA];
__device__ int   g_pos[NA];
__device__ float g_h1raw[(size_t)NA * 1024];
__device__ float g_h1act[(size_t)NA * 512];
__device__ float g_h2buf[(size_t)NA * 1024];
__device__ float g_hsraw[(size_t)T_TOK * 2048];
__device__ float g_hsact[(size_t)T_TOK * 1024];

// ---------------- gate ----------------
__global__ void zero_kernel() {
    if (threadIdx.x < E_NUM) g_counts[threadIdx.x] = 0;
}

__global__ void gate_kernel(const float* __restrict__ x,
                            const float* __restrict__ Wg) {
    int t = blockIdx.x;
    const float* xr = x + (size_t)t * D_IN;
    __shared__ float sx[D_IN];
    for (int i = threadIdx.x; i < D_IN; i += 128) sx[i] = xr[i];
    __syncthreads();

    int e = threadIdx.x >> 3;
    int sub = threadIdx.x & 7;
    const float* wr = Wg + (size_t)e * D_IN;
    float s = 0.f;
    for (int i = sub; i < D_IN; i += 8) s = fmaf(sx[i], wr[i], s);
    for (int o = 4; o; o >>= 1) s += __shfl_down_sync(0xffffffffu, s, o, 8);

    __shared__ float sc[E_NUM];
    if (sub == 0) sc[e] = s;
    __syncthreads();

    if (threadIdx.x == 0) {
        float mx = sc[0];
        #pragma unroll
        for (int i = 1; i < E_NUM; i++) mx = fmaxf(mx, sc[i]);
        float p[E_NUM];
        float den = 0.f;
        #pragma unroll
        for (int i = 0; i < E_NUM; i++) { p[i] = expf(sc[i] - mx); den += p[i]; }
        int i1 = 0; float v1 = p[0];
        #pragma unroll
        for (int i = 1; i < E_NUM; i++) if (p[i] > v1) { v1 = p[i]; i1 = i; }
        int i2 = -1; float v2 = -1.f;
        #pragma unroll
        for (int i = 0; i < E_NUM; i++)
            if (i != i1 && p[i] > v2) { v2 = p[i]; i2 = i; }
        float inv = 1.f / den;
        g_eidx[t * 2 + 0] = i1; g_w[t * 2 + 0] = v1 * inv;
        g_eidx[t * 2 + 1] = i2; g_w[t * 2 + 1] = v2 * inv;
        atomicAdd(&g_counts[i1], 1);
        atomicAdd(&g_counts[i2], 1);
    }
}

__global__ void scan_kernel() {
    if (threadIdx.x == 0) {
        int a = 0;
        for (int e = 0; e < E_NUM; e++) { g_offsets[e] = a; a += g_counts[e]; }
        g_offsets[E_NUM] = a;
    }
}

__global__ void compact_kernel() {
    int e = blockIdx.x;
    int base = g_offsets[e];
    __shared__ int warp_tot[8];
    __shared__ int running;
    if (threadIdx.x == 0) running = 0;
    __syncthreads();
    int lane = threadIdx.x & 31, wid = threadIdx.x >> 5;
    for (int c = 0; c < NA; c += 256) {
        int i = c + threadIdx.x;
        bool f = (g_eidx[i] == e);
        unsigned bal = __ballot_sync(0xffffffffu, f);
        int pre = __popc(bal & ((1u << lane) - 1u));
        if (lane == 0) warp_tot[wid] = __popc(bal);
        __syncthreads();
        int woff = 0, ctot = 0;
        #pragma unroll
        for (int w = 0; w < 8; w++) {
            int v = warp_tot[w];
            if (w < wid) woff += v;
            ctot += v;
        }
        if (f) {
            int pos = base + running + woff + pre;
            g_perm[pos] = i;
            g_pos[i] = pos;
        }
        __syncthreads();
        if (threadIdx.x == 0) running += ctot;
        __syncthreads();
    }
}

// ---------------- tf32 tensor-core GEMM ----------------
// Block 128x128, BK=32, 8 warps, warp tile 64x32 (4x4 m16n8k8).
// MODE 0: routed fc1, MODE 1: routed fc2 (weighted), MODE 2: shared fc1, MODE 3: shared fc2
#define BM 128
#define BN 128
#define BK 32
#define AS_STRIDE 36   // conflict-free: 36 mod 32 = 4
#define BS_STRIDE 136  // conflict-free: 136 mod 32 = 8

__device__ __forceinline__ uint32_t f2tf32(float x) {
    uint32_t u;
    asm("cvt.rna.tf32.f32 %0, %1;" : "=r"(u) : "f"(x));
    return u;
}

__device__ __forceinline__ void mma_tf32(float c[4], const uint32_t a[4], const uint32_t b[2]) {
    asm volatile(
        "mma.sync.aligned.m16n8k8.row.col.f32.tf32.tf32.f32 "
        "{%0,%1,%2,%3}, {%4,%5,%6,%7}, {%8,%9}, {%0,%1,%2,%3};"
        : "+f"(c[0]), "+f"(c[1]), "+f"(c[2]), "+f"(c[3])
        : "r"(a[0]), "r"(a[1]), "r"(a[2]), "r"(a[3]), "r"(b[0]), "r"(b[1]));
}

template <int MODE>
__global__ __launch_bounds__(256)
void mma_gemm_kernel(const float* __restrict__ A,
                     const float* __restrict__ Bmat,
                     float* __restrict__ Cout) {
    int cnt, base = 0, Kdim, ldb;
    const float* Bp;
    if constexpr (MODE == 0) {
        int e = blockIdx.z; cnt = g_counts[e]; base = g_offsets[e];
        Kdim = 1024; ldb = 1024; Bp = Bmat + (size_t)e * 1024 * 1024;
    } else if constexpr (MODE == 1) {
        int e = blockIdx.z; cnt = g_counts[e]; base = g_offsets[e];
        Kdim = 512; ldb = 1024; Bp = Bmat + (size_t)e * 512 * 1024;
    } else if constexpr (MODE == 2) {
        cnt = T_TOK; Kdim = 1024; ldb = 2048; Bp = Bmat;
    } else {
        cnt = T_TOK; Kdim = 1024; ldb = 1024; Bp = Bmat;
    }
    int m0 = blockIdx.y * BM;
    if (m0 >= cnt) return;
    int n0 = blockIdx.x * BN;

    __shared__ float As[BM][AS_STRIDE];   // m-major [m][k]
    __shared__ float Bs[BK][BS_STRIDE];   // k-major [k][n]

    int tid = threadIdx.x;
    int w = tid >> 5, lane = tid & 31;
    int wm = (w >> 2) * 64;          // warp m offset (0/64)
    int wn = (w & 3) * 32;           // warp n offset (0/32/64/96)
    int g = lane >> 2;               // groupID 0..7
    int tg = lane & 3;               // thread-in-group 0..3

    // ---- A loader: 4 float4 per thread over [128 rows][8 f4-cols]
    int a_r = tid >> 3;              // base row 0..31 (+32q)
    int a_c = (tid & 7) << 2;        // k offset (float index)
    const float* arow[4];
    bool avalid[4];
    #pragma unroll
    for (int q = 0; q < 4; q++) {
        int row = a_r + 32 * q;
        int gr = m0 + row;
        bool v = gr < cnt;
        avalid[q] = v;
        const float* p = nullptr;
        if (v) {
            if constexpr (MODE == 0) {
                int tok = g_perm[base + gr] >> 1;
                p = A + (size_t)tok * 1024;
            } else if constexpr (MODE == 1) {
                p = g_h1act + (size_t)(base + gr) * 512;
            } else if constexpr (MODE == 2) {
                p = A + (size_t)gr * 1024;
            } else {
                p = g_hsact + (size_t)gr * 1024;
            }
        }
        arow[q] = p;
    }
    // ---- B loader: 4 float4 per thread over [32 k][32 f4-cols]
    int b_k = tid >> 5;              // base k 0..7 (+8q)
    int b_c = (tid & 31) << 2;       // n offset

    float4 pa[4], pb[4];
    auto load_tile = [&](int k0) {
        #pragma unroll
        for (int q = 0; q < 4; q++) {
            pa[q] = avalid[q] ? *reinterpret_cast<const float4*>(arow[q] + k0 + a_c)
                              : make_float4(0.f, 0.f, 0.f, 0.f);
            pb[q] = *reinterpret_cast<const float4*>(
                Bp + (size_t)(k0 + b_k + 8 * q) * ldb + n0 + b_c);
        }
    };
    auto store_tile = [&]() {
        #pragma unroll
        for (int q = 0; q < 4; q++) {
            int row = a_r + 32 * q;
            float4 v = pa[q];
            v.x = __uint_as_float(f2tf32(v.x));
            v.y = __uint_as_float(f2tf32(v.y));
            v.z = __uint_as_float(f2tf32(v.z));
            v.w = __uint_as_float(f2tf32(v.w));
            *reinterpret_cast<float4*>(&As[row][a_c]) = v;
            float4 u = pb[q];
            u.x = __uint_as_float(f2tf32(u.x));
            u.y = __uint_as_float(f2tf32(u.y));
            u.z = __uint_as_float(f2tf32(u.z));
            u.w = __uint_as_float(f2tf32(u.w));
            *reinterpret_cast<float4*>(&Bs[b_k + 8 * q][b_c]) = u;
        }
    };

    float acc[4][4][4];
    #pragma unroll
    for (int mi = 0; mi < 4; mi++)
        #pragma unroll
        for (int ni = 0; ni < 4; ni++)
            #pragma unroll
            for (int r = 0; r < 4; r++) acc[mi][ni][r] = 0.f;

    load_tile(0);
    store_tile();
    __syncthreads();

    for (int k0 = BK; k0 <= Kdim; k0 += BK) {
        bool more = (k0 < Kdim);
        if (more) load_tile(k0);
        // compute current tile: 4 k-steps of 8
        #pragma unroll
        for (int ks = 0; ks < 4; ks++) {
            int k = ks * 8;
            uint32_t afr[4][4];
            #pragma unroll
            for (int mi = 0; mi < 4; mi++) {
                int r = wm + mi * 16 + g;
                afr[mi][0] = __float_as_uint(As[r][k + tg]);
                afr[mi][1] = __float_as_uint(As[r + 8][k + tg]);
                afr[mi][2] = __float_as_uint(As[r][k + tg + 4]);
                afr[mi][3] = __float_as_uint(As[r + 8][k + tg + 4]);
            }
            uint32_t bfr[4][2];
            #pragma unroll
            for (int ni = 0; ni < 4; ni++) {
                int c = wn + ni * 8 + g;
                bfr[ni][0] = __float_as_uint(Bs[k + tg][c]);
                bfr[ni][1] = __float_as_uint(Bs[k + tg + 4][c]);
            }
            #pragma unroll
            for (int mi = 0; mi < 4; mi++)
                #pragma unroll
                for (int ni = 0; ni < 4; ni++)
                    mma_tf32(acc[mi][ni], afr[mi], bfr[ni]);
        }
        __syncthreads();
        if (more) {
            store_tile();
            __syncthreads();
        }
    }

    // ---- epilogue ----
    #pragma unroll
    for (int mi = 0; mi < 4; mi++) {
        int r0 = m0 + wm + mi * 16 + g;
        int r1 = r0 + 8;
        bool v0 = r0 < cnt, v1 = r1 < cnt;
        float w0 = 1.f, w1 = 1.f;
        float *dst0 = nullptr, *dst1 = nullptr;
        if constexpr (MODE == 0) {
            if (v0) dst0 = g_h1raw + (size_t)(base + r0) * 1024;
            if (v1) dst1 = g_h1raw + (size_t)(base + r1) * 1024;
        } else if constexpr (MODE == 1) {
            if (v0) { w0 = g_w[g_perm[base + r0]]; dst0 = g_h2buf + (size_t)(base + r0) * 1024; }
            if (v1) { w1 = g_w[g_perm[base + r1]]; dst1 = g_h2buf + (size_t)(base + r1) * 1024; }
        } else if constexpr (MODE == 2) {
            if (v0) dst0 = g_hsraw + (size_t)r0 * 2048;
            if (v1) dst1 = g_hsraw + (size_t)r1 * 2048;
        } else {
            if (v0) dst0 = Cout + (size_t)r0 * 1024;
            if (v1) dst1 = Cout + (size_t)r1 * 1024;
        }
        #pragma unroll
        for (int ni = 0; ni < 4; ni++) {
            int col = n0 + wn + ni * 8 + 2 * tg;
            if (v0) {
                float2 c01 = make_float2(w0 * acc[mi][ni][0], w0 * acc[mi][ni][1]);
                *reinterpret_cast<float2*>(dst0 + col) = c01;
            }
            if (v1) {
                float2 c23 = make_float2(w1 * acc[mi][ni][2], w1 * acc[mi][ni][3]);
                *reinterpret_cast<float2*>(dst1 + col) = c23;
            }
        }
    }
}

// ---------------- activations: u * silu(g) ----------------
__device__ __forceinline__ float silu_mul(float u, float g) {
    return u * (g / (1.f + expf(-g)));
}

__global__ void act_routed_kernel() {
    int i = blockIdx.x * blockDim.x + threadIdx.x;
    if (i >= NA * 128) return;
    int p = i >> 7, h4 = i & 127;
    const float* rowp = g_h1raw + (size_t)p * 1024;
    float4 u = reinterpret_cast<const float4*>(rowp)[h4];
    float4 g = reinterpret_cast<const float4*>(rowp + 512)[h4];
    float4 r;
    r.x = silu_mul(u.x, g.x); r.y = silu_mul(u.y, g.y);
    r.z = silu_mul(u.z, g.z); r.w = silu_mul(u.w, g.w);
    reinterpret_cast<float4*>(g_h1act + (size_t)p * 512)[h4] = r;
}

__global__ void act_shared_kernel() {
    int i = blockIdx.x * blockDim.x + threadIdx.x;
    if (i >= T_TOK * 256) return;
    int t = i >> 8, h4 = i & 255;
    const float* rowp = g_hsraw + (size_t)t * 2048;
    float4 u = reinterpret_cast<const float4*>(rowp)[h4];
    float4 g = reinterpret_cast<const float4*>(rowp + 1024)[h4];
    float4 r;
    r.x = silu_mul(u.x, g.x); r.y = silu_mul(u.y, g.y);
    r.z = silu_mul(u.z, g.z); r.w = silu_mul(u.w, g.w);
    reinterpret_cast<float4*>(g_hsact + (size_t)t * 1024)[h4] = r;
}

// ---------------- deterministic combine ----------------
__global__ void combine_kernel(float* __restrict__ out) {
    int i = blockIdx.x * blockDim.x + threadIdx.x;
    if (i >= T_TOK * 256) return;
    int t = i >> 8, c4 = i & 255;
    int p0 = g_pos[2 * t + 0];
    int p1 = g_pos[2 * t + 1];
    float4 a = reinterpret_cast<const float4*>(g_h2buf + (size_t)p0 * 1024)[c4];
    float4 b = reinterpret_cast<const float4*>(g_h2buf + (size_t)p1 * 1024)[c4];
    float4* o = reinterpret_cast<float4*>(out + (size_t)t * 1024) + c4;
    float4 v = *o;
    v.x += a.x + b.x; v.y += a.y + b.y; v.z += a.z + b.z; v.w += a.w + b.w;
    *o = v;
}

// ---------------- launch ----------------
extern "C" void kernel_launch(void* const* d_in, const int* in_sizes, int n_in,
                              void* d_out, int out_size) {
    (void)in_sizes; (void)n_in; (void)out_size;
    const float* x   = (const float*)d_in[0];
    const float* Wg  = (const float*)d_in[1];
    const float* W1  = (const float*)d_in[2];
    const float* W2  = (const float*)d_in[3];
    const float* Ws1 = (const float*)d_in[4];
    const float* Ws2 = (const float*)d_in[5];
    float* out = (float*)d_out;

    zero_kernel<<<1, 32>>>();
    gate_kernel<<<T_TOK, 128>>>(x, Wg);
    scan_kernel<<<1, 32>>>();
    compact_kernel<<<E_NUM, 256>>>();

    // routed fc1: per-expert [cnt,1024] x [1024,1024]
    mma_gemm_kernel<0><<<dim3(1024 / BN, T_TOK / BM, E_NUM), 256>>>(x, W1, nullptr);
    act_routed_kernel<<<(NA * 128 + 255) / 256, 256>>>();
    // routed fc2: per-expert [cnt,512] x [512,1024] -> weighted
    mma_gemm_kernel<1><<<dim3(1024 / BN, T_TOK / BM, E_NUM), 256>>>(nullptr, W2, nullptr);

    // shared fc1: [2048,1024] x [1024,2048]
    mma_gemm_kernel<2><<<dim3(2048 / BN, T_TOK / BM, 1), 256>>>(x, Ws1, nullptr);
    act_shared_kernel<<<(T_TOK * 256 + 255) / 256, 256>>>();
    // shared fc2: [2048,1024] x [1024,1024] -> out
    mma_gemm_kernel<3><<<dim3(1024 / BN, T_TOK / BM, 1), 256>>>(nullptr, Ws2, out);

    combine_kernel<<<(T_TOK * 256 + 255) / 256, 256>>>(out);
}

// round 5
// speedup vs baseline: 3.2592x; 1.0247x over previous
#include <cuda_runtime.h>
#include <math.h>
#include <stdint.h>

// Problem constants
#define T_TOK 2048      // B*S tokens
#define D_IN  1024      // model dim
#define E_NUM 16        // routed experts
#define TOPK  2
#define H_DIM 512       // expert intermediate
#define HS_DIM 1024     // shared expert hidden (2*H)
#define NA    (T_TOK * TOPK)   // 4096 assignments

// ---------------- scratch (device globals, allocation-free) ----------------
__device__ float g_w[NA];
__device__ int   g_eidx[NA];
__device__ int   g_counts[E_NUM];
__device__ int   g_offsets[E_NUM + 1];
__device__ int   g_perm[NA];
__device__ int   g_pos[NA];
__device__ float g_h1raw[(size_t)NA * 1024];
__device__ float g_h1act[(size_t)NA * 512];
__device__ float g_h2buf[(size_t)NA * 1024];
__device__ float g_hsraw[(size_t)T_TOK * 2048];
__device__ float g_hsact[(size_t)T_TOK * 1024];

// ---------------- gate ----------------
__global__ void zero_kernel() {
    if (threadIdx.x < E_NUM) g_counts[threadIdx.x] = 0;
}

__global__ void gate_kernel(const float* __restrict__ x,
                            const float* __restrict__ Wg) {
    int t = blockIdx.x;
    const float* xr = x + (size_t)t * D_IN;
    __shared__ float sx[D_IN];
    for (int i = threadIdx.x; i < D_IN; i += 128) sx[i] = xr[i];
    __syncthreads();

    int e = threadIdx.x >> 3;
    int sub = threadIdx.x & 7;
    const float* wr = Wg + (size_t)e * D_IN;
    float s = 0.f;
    for (int i = sub; i < D_IN; i += 8) s = fmaf(sx[i], wr[i], s);
    for (int o = 4; o; o >>= 1) s += __shfl_down_sync(0xffffffffu, s, o, 8);

    __shared__ float sc[E_NUM];
    if (sub == 0) sc[e] = s;
    __syncthreads();

    if (threadIdx.x == 0) {
        float mx = sc[0];
        #pragma unroll
        for (int i = 1; i < E_NUM; i++) mx = fmaxf(mx, sc[i]);
        float p[E_NUM];
        float den = 0.f;
        #pragma unroll
        for (int i = 0; i < E_NUM; i++) { p[i] = expf(sc[i] - mx); den += p[i]; }
        int i1 = 0; float v1 = p[0];
        #pragma unroll
        for (int i = 1; i < E_NUM; i++) if (p[i] > v1) { v1 = p[i]; i1 = i; }
        int i2 = -1; float v2 = -1.f;
        #pragma unroll
        for (int i = 0; i < E_NUM; i++)
            if (i != i1 && p[i] > v2) { v2 = p[i]; i2 = i; }
        float inv = 1.f / den;
        g_eidx[t * 2 + 0] = i1; g_w[t * 2 + 0] = v1 * inv;
        g_eidx[t * 2 + 1] = i2; g_w[t * 2 + 1] = v2 * inv;
        atomicAdd(&g_counts[i1], 1);
        atomicAdd(&g_counts[i2], 1);
    }
}

__global__ void scan_kernel() {
    if (threadIdx.x == 0) {
        int a = 0;
        for (int e = 0; e < E_NUM; e++) { g_offsets[e] = a; a += g_counts[e]; }
        g_offsets[E_NUM] = a;
    }
}

// stable per-expert compaction, 512 threads
__global__ void compact_kernel() {
    int e = blockIdx.x;
    int base = g_offsets[e];
    __shared__ int warp_tot[16];
    __shared__ int running;
    if (threadIdx.x == 0) running = 0;
    __syncthreads();
    int lane = threadIdx.x & 31, wid = threadIdx.x >> 5;
    for (int c = 0; c < NA; c += 512) {
        int i = c + threadIdx.x;
        bool f = (g_eidx[i] == e);
        unsigned bal = __ballot_sync(0xffffffffu, f);
        int pre = __popc(bal & ((1u << lane) - 1u));
        if (lane == 0) warp_tot[wid] = __popc(bal);
        __syncthreads();
        int woff = 0, ctot = 0;
        #pragma unroll
        for (int w = 0; w < 16; w++) {
            int v = warp_tot[w];
            if (w < wid) woff += v;
            ctot += v;
        }
        if (f) {
            int pos = base + running + woff + pre;
            g_perm[pos] = i;
            g_pos[i] = pos;
        }
        __syncthreads();
        if (threadIdx.x == 0) running += ctot;
        __syncthreads();
    }
}

// ---------------- tf32 tensor-core GEMM, fragment-order smem ----------------
// Block 128x128, BK=32, 8 warps, warp tile 64x32 (4x4 m16n8k8).
// A smem: fragment order [mtile(8)][ktile(4)][lane(32)][4] w/ ktile pad 4 floats
// B smem: fragment order [ntile(16)][ktile(4)][lane(32)][2] w/ ntile pad 2 floats
#define BM 128
#define BN 128
#define BK 32
#define A_KT_STRIDE 132          // 32*4 + 4 pad floats (16B, keeps .128 align)
#define A_MT_STRIDE (4 * A_KT_STRIDE)
#define B_KT_STRIDE 64
#define B_NT_STRIDE (4 * B_KT_STRIDE + 2)   // +2 floats pad (8B align kept)

__device__ __forceinline__ uint32_t f2tf32(float x) {
    uint32_t u;
    asm("cvt.rna.tf32.f32 %0, %1;" : "=r"(u) : "f"(x));
    return u;
}

__device__ __forceinline__ void mma_tf32(float c[4], const uint32_t a[4], const uint32_t b[2]) {
    asm volatile(
        "mma.sync.aligned.m16n8k8.row.col.f32.tf32.tf32.f32 "
        "{%0,%1,%2,%3}, {%4,%5,%6,%7}, {%8,%9}, {%0,%1,%2,%3};"
        : "+f"(c[0]), "+f"(c[1]), "+f"(c[2]), "+f"(c[3])
        : "r"(a[0]), "r"(a[1]), "r"(a[2]), "r"(a[3]), "r"(b[0]), "r"(b[1]));
}

template <int MODE>
__global__ __launch_bounds__(256)
void mma_gemm_kernel(const float* __restrict__ A,
                     const float* __restrict__ Bmat,
                     float* __restrict__ Cout) {
    int cnt, base = 0, Kdim, ldb;
    const float* Bp;
    if constexpr (MODE == 0) {
        int e = blockIdx.z; cnt = g_counts[e]; base = g_offsets[e];
        Kdim = 1024; ldb = 1024; Bp = Bmat + (size_t)e * 1024 * 1024;
    } else if constexpr (MODE == 1) {
        int e = blockIdx.z; cnt = g_counts[e]; base = g_offsets[e];
        Kdim = 512; ldb = 1024; Bp = Bmat + (size_t)e * 512 * 1024;
    } else if constexpr (MODE == 2) {
        cnt = T_TOK; Kdim = 1024; ldb = 2048; Bp = Bmat;
    } else {
        cnt = T_TOK; Kdim = 1024; ldb = 1024; Bp = Bmat;
    }
    int m0 = blockIdx.y * BM;
    if (m0 >= cnt) return;
    int n0 = blockIdx.x * BN;

    __shared__ float As_f[8 * A_MT_STRIDE];    // 4224 floats = 16896 B
    __shared__ float Bs_f[16 * B_NT_STRIDE];   // 4128 floats = 16512 B

    int tid = threadIdx.x;
    int w = tid >> 5, lane = tid & 31;
    int mtb = (w >> 2) * 4;          // warp mtile base (0/4)
    int ntb = (w & 3) * 4;           // warp ntile base (0/4/8/12)
    int g = lane >> 2;               // groupID 0..7
    int tg = lane & 3;               // thread-in-group 0..3

    // ---- A loader indices: 4 float4 per thread over [128 rows][8 f4-cols]
    int a_r = tid >> 3;              // base row 0..31 (+32q)
    int a_c = (tid & 7) << 2;        // k offset (float index), multiple of 4
    int a_kt = a_c >> 3;
    int a_hk = (a_c >> 2) & 1;
    const float* arow[4];
    bool avalid[4];
    int a_sbase[4];                  // smem float index base per q (excl. j term)
    #pragma unroll
    for (int q = 0; q < 4; q++) {
        int row = a_r + 32 * q;
        int gr = m0 + row;
        bool v = gr < cnt;
        avalid[q] = v;
        const float* p = nullptr;
        if (v) {
            if constexpr (MODE == 0) {
                int tok = g_perm[base + gr] >> 1;
                p = A + (size_t)tok * 1024;
            } else if constexpr (MODE == 1) {
                p = g_h1act + (size_t)(base + gr) * 512;
            } else if constexpr (MODE == 2) {
                p = A + (size_t)gr * 1024;
            } else {
                p = g_hsact + (size_t)gr * 1024;
            }
        }
        arow[q] = p;
        int mt = row >> 4, r = row & 15;
        int gg = r & 7, hm = r >> 3;
        a_sbase[q] = mt * A_MT_STRIDE + a_kt * A_KT_STRIDE + (gg << 4) + hm + 2 * a_hk;
    }
    // ---- B loader indices: 4 float4 per thread over [32 k][32 f4-cols]
    int b_k = tid >> 5;              // base k 0..7 (+8q)
    int b_c = (tid & 31) << 2;       // n offset, multiple of 4
    int b_nt = b_c >> 3;
    int b_g0 = b_c & 7;              // 0 or 4
    int b_sbase[4];
    #pragma unroll
    for (int q = 0; q < 4; q++) {
        int k = b_k + 8 * q;
        int kt = k >> 3, kk = k & 7;
        int btg = kk & 3, hk = kk >> 2;
        b_sbase[q] = b_nt * B_NT_STRIDE + kt * B_KT_STRIDE + ((b_g0 * 4 + btg) << 1) + hk;
    }

    float4 pa[4], pb[4];
    auto load_tile = [&](int k0) {
        #pragma unroll
        for (int q = 0; q < 4; q++) {
            pa[q] = avalid[q] ? *reinterpret_cast<const float4*>(arow[q] + k0 + a_c)
                              : make_float4(0.f, 0.f, 0.f, 0.f);
            pb[q] = *reinterpret_cast<const float4*>(
                Bp + (size_t)(k0 + b_k + 8 * q) * ldb + n0 + b_c);
        }
    };
    auto store_tile = [&]() {
        #pragma unroll
        for (int q = 0; q < 4; q++) {
            // A scatter: 4 lanes (j = k position tg), stride 16 floats
            As_f[a_sbase[q] + 0]  = __uint_as_float(f2tf32(pa[q].x));
            As_f[a_sbase[q] + 4]  = __uint_as_float(f2tf32(pa[q].y));
            As_f[a_sbase[q] + 8]  = __uint_as_float(f2tf32(pa[q].z));
            As_f[a_sbase[q] + 12] = __uint_as_float(f2tf32(pa[q].w));
            // B scatter: 4 lanes (j = n position g), stride 8 floats
            Bs_f[b_sbase[q] + 0]  = __uint_as_float(f2tf32(pb[q].x));
            Bs_f[b_sbase[q] + 8]  = __uint_as_float(f2tf32(pb[q].y));
            Bs_f[b_sbase[q] + 16] = __uint_as_float(f2tf32(pb[q].z));
            Bs_f[b_sbase[q] + 24] = __uint_as_float(f2tf32(pb[q].w));
        }
    };

    float acc[4][4][4];
    #pragma unroll
    for (int mi = 0; mi < 4; mi++)
        #pragma unroll
        for (int ni = 0; ni < 4; ni++)
            #pragma unroll
            for (int r = 0; r < 4; r++) acc[mi][ni][r] = 0.f;

    load_tile(0);
    store_tile();
    __syncthreads();

    for (int k0 = BK; k0 <= Kdim; k0 += BK) {
        bool more = (k0 < Kdim);
        if (more) load_tile(k0);   // LDG latency covered by the MMA block below
        #pragma unroll
        for (int ks = 0; ks < 4; ks++) {
            float4 af[4];
            float2 bf[4];
            #pragma unroll
            for (int mi = 0; mi < 4; mi++)
                af[mi] = *reinterpret_cast<const float4*>(
                    &As_f[(mtb + mi) * A_MT_STRIDE + ks * A_KT_STRIDE + lane * 4]);
            #pragma unroll
            for (int ni = 0; ni < 4; ni++)
                bf[ni] = *reinterpret_cast<const float2*>(
                    &Bs_f[(ntb + ni) * B_NT_STRIDE + ks * B_KT_STRIDE + lane * 2]);
            #pragma unroll
            for (int mi = 0; mi < 4; mi++) {
                uint32_t a[4] = {__float_as_uint(af[mi].x), __float_as_uint(af[mi].y),
                                 __float_as_uint(af[mi].z), __float_as_uint(af[mi].w)};
                #pragma unroll
                for (int ni = 0; ni < 4; ni++) {
                    uint32_t b[2] = {__float_as_uint(bf[ni].x), __float_as_uint(bf[ni].y)};
                    mma_tf32(acc[mi][ni], a, b);
                }
            }
        }
        if (!more) break;
        __syncthreads();
        store_tile();
        __syncthreads();
    }

    // ---- epilogue ----
    #pragma unroll
    for (int mi = 0; mi < 4; mi++) {
        int lr0 = (mtb >> 2) * 64 + mi * 16 + g;   // local row within 128 tile
        int r0 = m0 + lr0;
        int r1 = r0 + 8;
        bool v0 = r0 < cnt, v1 = r1 < cnt;
        float w0 = 1.f, w1 = 1.f;
        float *dst0 = nullptr, *dst1 = nullptr;
        const float *add0a = nullptr, *add0b = nullptr, *add1a = nullptr, *add1b = nullptr;
        if constexpr (MODE == 0) {
            if (v0) dst0 = g_h1raw + (size_t)(base + r0) * 1024;
            if (v1) dst1 = g_h1raw + (size_t)(base + r1) * 1024;
        } else if constexpr (MODE == 1) {
            if (v0) { w0 = g_w[g_perm[base + r0]]; dst0 = g_h2buf + (size_t)(base + r0) * 1024; }
            if (v1) { w1 = g_w[g_perm[base + r1]]; dst1 = g_h2buf + (size_t)(base + r1) * 1024; }
        } else if constexpr (MODE == 2) {
            if (v0) dst0 = g_hsraw + (size_t)r0 * 2048;
            if (v1) dst1 = g_hsraw + (size_t)r1 * 2048;
        } else {
            // MODE 3: out = shared_fc2 + routed(k0) + routed(k1)  (fused combine)
            if (v0) {
                dst0 = Cout + (size_t)r0 * 1024;
                add0a = g_h2buf + (size_t)g_pos[2 * r0 + 0] * 1024;
                add0b = g_h2buf + (size_t)g_pos[2 * r0 + 1] * 1024;
            }
            if (v1) {
                dst1 = Cout + (size_t)r1 * 1024;
                add1a = g_h2buf + (size_t)g_pos[2 * r1 + 0] * 1024;
                add1b = g_h2buf + (size_t)g_pos[2 * r1 + 1] * 1024;
            }
        }
        int wn = (ntb >> 2) * 32;
        #pragma unroll
        for (int ni = 0; ni < 4; ni++) {
            int col = n0 + wn + ni * 8 + 2 * tg;
            if (v0) {
                float c0 = w0 * acc[mi][ni][0], c1 = w0 * acc[mi][ni][1];
                if constexpr (MODE == 3) {
                    float2 aa = *reinterpret_cast<const float2*>(add0a + col);
                    float2 bb = *reinterpret_cast<const float2*>(add0b + col);
                    c0 += aa.x + bb.x; c1 += aa.y + bb.y;
                }
                *reinterpret_cast<float2*>(dst0 + col) = make_float2(c0, c1);
            }
            if (v1) {
                float c2 = w1 * acc[mi][ni][2], c3 = w1 * acc[mi][ni][3];
                if constexpr (MODE == 3) {
                    float2 aa = *reinterpret_cast<const float2*>(add1a + col);
                    float2 bb = *reinterpret_cast<const float2*>(add1b + col);
                    c2 += aa.x + bb.x; c3 += aa.y + bb.y;
                }
                *reinterpret_cast<float2*>(dst1 + col) = make_float2(c2, c3);
            }
        }
    }
}

// ---------------- activations: u * silu(g) ----------------
__device__ __forceinline__ float silu_mul(float u, float g) {
    return u * (g / (1.f + expf(-g)));
}

__global__ void act_routed_kernel() {
    int i = blockIdx.x * blockDim.x + threadIdx.x;
    if (i >= NA * 128) return;
    int p = i >> 7, h4 = i & 127;
    const float* rowp = g_h1raw + (size_t)p * 1024;
    float4 u = reinterpret_cast<const float4*>(rowp)[h4];
    float4 g = reinterpret_cast<const float4*>(rowp + 512)[h4];
    float4 r;
    r.x = silu_mul(u.x, g.x); r.y = silu_mul(u.y, g.y);
    r.z = silu_mul(u.z, g.z); r.w = silu_mul(u.w, g.w);
    reinterpret_cast<float4*>(g_h1act + (size_t)p * 512)[h4] = r;
}

__global__ void act_shared_kernel() {
    int i = blockIdx.x * blockDim.x + threadIdx.x;
    if (i >= T_TOK * 256) return;
    int t = i >> 8, h4 = i & 255;
    const float* rowp = g_hsraw + (size_t)t * 2048;
    float4 u = reinterpret_cast<const float4*>(rowp)[h4];
    float4 g = reinterpret_cast<const float4*>(rowp + 1024)[h4];
    float4 r;
    r.x = silu_mul(u.x, g.x); r.y = silu_mul(u.y, g.y);
    r.z = silu_mul(u.z, g.z); r.w = silu_mul(u.w, g.w);
    reinterpret_cast<float4*>(g_hsact + (size_t)t * 1024)[h4] = r;
}

// ---------------- launch ----------------
extern "C" void kernel_launch(void* const* d_in, const int* in_sizes, int n_in,
                              void* d_out, int out_size) {
    (void)in_sizes; (void)n_in; (void)out_size;
    const float* x   = (const float*)d_in[0];
    const float* Wg  = (const float*)d_in[1];
    const float* W1  = (const float*)d_in[2];
    const float* W2  = (const float*)d_in[3];
    const float* Ws1 = (const float*)d_in[4];
    const float* Ws2 = (const float*)d_in[5];
    float* out = (float*)d_out;

    zero_kernel<<<1, 32>>>();
    gate_kernel<<<T_TOK, 128>>>(x, Wg);
    scan_kernel<<<1, 32>>>();
    compact_kernel<<<E_NUM, 512>>>();

    // routed fc1: per-expert [cnt,1024] x [1024,1024]
    mma_gemm_kernel<0><<<dim3(1024 / BN, T_TOK / BM, E_NUM), 256>>>(x, W1, nullptr);
    act_routed_kernel<<<(NA * 128 + 255) / 256, 256>>>();
    // routed fc2: per-expert [cnt,512] x [512,1024] -> weighted
    mma_gemm_kernel<1><<<dim3(1024 / BN, T_TOK / BM, E_NUM), 256>>>(nullptr, W2, nullptr);

    // shared fc1: [2048,1024] x [1024,2048]
    mma_gemm_kernel<2><<<dim3(2048 / BN, T_TOK / BM, 1), 256>>>(x, Ws1, nullptr);
    act_shared_kernel<<<(T_TOK * 256 + 255) / 256, 256>>>();
    // shared fc2: [2048,1024] x [1024,1024] -> out (+ fused routed combine)
    mma_gemm_kernel<3><<<dim3(1024 / BN, T_TOK / BM, 1), 256>>>(nullptr, Ws2, out);
}